// round 13
// baseline (speedup 1.0000x reference)
#include <cuda_runtime.h>
#include <cuda_bf16.h>
#include <cstdint>

#define B_   8
#define C_   64
#define H_   128
#define W_   416
#define OH_  (4 * H_)
#define OW_  (4 * W_)
#define HW_  (H_ * W_)

// Scratch h: conv3x3+relu output, CHANNEL-LAST bf16: [b][y][x][ci] (~54.5 MB).
__device__ __nv_bfloat16 g_h[(size_t)B_ * H_ * W_ * C_];
// Pre-built B-fragment table: [(tap*4+kc)*2+warpN][lane][8] uint32 (72 KB).
__device__ uint32_t g_wpack[72 * 32 * 8];

// ---------------------------------------------------------------------------
// helpers (legacy mma.sync / ldmatrix — compile for plain compute_103)
// ---------------------------------------------------------------------------
__device__ __forceinline__ uint32_t smem_u32(const void* p) {
    uint32_t a;
    asm("{ .reg .u64 t; cvta.to.shared.u64 t, %1; cvt.u32.u64 %0, t; }"
        : "=r"(a) : "l"(p));
    return a;
}

__device__ __forceinline__ void mma_bf16(float* d, const uint32_t* a,
                                         uint32_t b0, uint32_t b1) {
    asm volatile(
        "mma.sync.aligned.m16n8k16.row.col.f32.bf16.bf16.f32 "
        "{%0,%1,%2,%3}, {%4,%5,%6,%7}, {%8,%9}, {%0,%1,%2,%3};"
        : "+f"(d[0]), "+f"(d[1]), "+f"(d[2]), "+f"(d[3])
        : "r"(a[0]), "r"(a[1]), "r"(a[2]), "r"(a[3]), "r"(b0), "r"(b1));
}

__device__ __forceinline__ void ldmx4(uint32_t* r, uint32_t addr) {
    asm volatile(
        "ldmatrix.sync.aligned.m8n8.x4.shared.b16 {%0,%1,%2,%3}, [%4];"
        : "=r"(r[0]), "=r"(r[1]), "=r"(r[2]), "=r"(r[3]) : "r"(addr));
}

#define SPADB  144                      // bytes per ci-row (72 bf16 slots)
#define WTAP   9216                     // per-tap weights: 64*144

// ---------------------------------------------------------------------------
// Kernel W: repack w1 into per-lane B-fragment words via real ldmatrix.
// 9 CTAs (one per tap); each stages its 9KB tap tile, 8 warps each emit one
// (kc, warpN) unit.
// ---------------------------------------------------------------------------
#define SMEM_W_BYTES WTAP

__global__ __launch_bounds__(256) void repack_w1_kernel(
    const float* __restrict__ w1)
{
    extern __shared__ char smw[];
    const uint32_t sbase = smem_u32(smw);
    const int tap = blockIdx.x;
    const int tid = threadIdx.x;
    const int wid = tid >> 5;
    const int lane = tid & 31;

    for (int j = tid; j < 64 * 32; j += 256) {
        int co  = j >> 5;
        int ci2 = j & 31;
        const float* wp = w1 + co * 576 + ci2 * 18 + tap;
        __nv_bfloat162 v2 = __floats2bfloat162_rn(wp[0], wp[9]);
        *reinterpret_cast<uint32_t*>(smw + co * SPADB + ci2 * 4) =
            *reinterpret_cast<uint32_t*>(&v2);
    }
    __syncthreads();

    const uint32_t b_loff = (uint32_t)((lane & 7) * SPADB + ((lane >> 3) & 1) * 16
                                       + ((lane >> 4) & 1) * (8 * SPADB));
    const int kc = wid >> 1;
    const int wn = wid & 1;
    const uint32_t wrow = sbase + (uint32_t)(wn * 32 * SPADB + kc * 32) + b_loff;
    uint32_t bf[8];
    ldmx4(bf, wrow);
    ldmx4(bf + 4, wrow + (uint32_t)(16 * SPADB));
    const int u = tap * 8 + kc * 2 + wn;     // == (tap*4+kc)*2 + wn
    uint32_t* dst = g_wpack + (size_t)u * 256 + lane * 8;
    *reinterpret_cast<uint4*>(dst)     = make_uint4(bf[0], bf[1], bf[2], bf[3]);
    *reinterpret_cast<uint4*>(dst + 4) = make_uint4(bf[4], bf[5], bf[6], bf[7]);
}

// ---------------------------------------------------------------------------
// Kernel A: conv3x3 (pad=1, no bias) + ReLU as bf16 implicit GEMM.
// CTA = 2 rows x 128 px x 64 co, 256 threads (8 warps: 4M x 2N), 2 CTAs/SM.
// Staging: interior via float4 LDG (32/thread) + 2 scalar halo columns.
// A-frags via ldmatrix; B-frags via 2 coalesced LDG.128 from g_wpack,
// double-buffered + prefetched 1 iter ahead.
// ---------------------------------------------------------------------------
#define SMEM_A_BYTES (4 * 130 * SPADB)      // 74880

__global__ __launch_bounds__(256, 2) void conv3x3_tc_kernel(
    const float* __restrict__ feat)
{
    extern __shared__ char sm[];
    const uint32_t sbase = smem_u32(sm);

    const int x0  = (blockIdx.x < 3) ? blockIdx.x * 128 : (W_ - 128);
    const int y0  = blockIdx.y * 2;
    const int b   = blockIdx.z;
    const int tid = threadIdx.x;
    const int wid = tid >> 5;
    const int lane = tid & 31;
    const int gid = lane >> 2;
    const int tig = lane & 3;

    const int warpM  = wid & 3;
    const int warpN  = wid >> 2;
    const int rowsel = warpM >> 1;
    const int xwbase = (warpM & 1) * 64;

    // ---- Stage feat rows y0-1 .. y0+2, interior as float4 ----
    // j -> (r, ci2, xg): gx = x0 + xg*4 .. +3, smem xi = xg*4+1 .. +4
    for (int j = tid; j < 4 * 32 * 32; j += 256) {
        int r   = j >> 10;
        int ci2 = (j >> 5) & 31;
        int xg  = j & 31;
        int yy  = y0 + r - 1;
        float4 f0 = make_float4(0.f, 0.f, 0.f, 0.f);
        float4 f1 = f0;
        if ((unsigned)yy < (unsigned)H_) {
            size_t o = ((size_t)(b * C_ + 2 * ci2) * H_ + yy) * W_ + x0 + xg * 4;
            f0 = *reinterpret_cast<const float4*>(feat + o);
            f1 = *reinterpret_cast<const float4*>(feat + o + (size_t)HW_);
        }
        char* dst = sm + (r * 130 + xg * 4 + 1) * SPADB + ci2 * 4;
        __nv_bfloat162 v;
        v = __floats2bfloat162_rn(f0.x, f1.x);
        *reinterpret_cast<uint32_t*>(dst)             = *reinterpret_cast<uint32_t*>(&v);
        v = __floats2bfloat162_rn(f0.y, f1.y);
        *reinterpret_cast<uint32_t*>(dst + SPADB)     = *reinterpret_cast<uint32_t*>(&v);
        v = __floats2bfloat162_rn(f0.z, f1.z);
        *reinterpret_cast<uint32_t*>(dst + 2 * SPADB) = *reinterpret_cast<uint32_t*>(&v);
        v = __floats2bfloat162_rn(f0.w, f1.w);
        *reinterpret_cast<uint32_t*>(dst + 3 * SPADB) = *reinterpret_cast<uint32_t*>(&v);
    }
    // ---- Halo columns xi=0 (gx=x0-1) and xi=129 (gx=x0+128) ----
    for (int j = tid; j < 4 * 32 * 2; j += 256) {
        int r   = j >> 6;
        int ci2 = (j >> 1) & 31;
        int hs  = j & 1;
        int yy  = y0 + r - 1;
        int gx  = hs ? (x0 + 128) : (x0 - 1);
        int xi  = hs ? 129 : 0;
        float f0 = 0.f, f1 = 0.f;
        if ((unsigned)yy < (unsigned)H_ && (unsigned)gx < (unsigned)W_) {
            size_t o = ((size_t)(b * C_ + 2 * ci2) * H_ + yy) * W_ + gx;
            f0 = feat[o];
            f1 = feat[o + (size_t)HW_];
        }
        __nv_bfloat162 v2 = __floats2bfloat162_rn(f0, f1);
        *reinterpret_cast<uint32_t*>(sm + (r * 130 + xi) * SPADB + ci2 * 4) =
            *reinterpret_cast<uint32_t*>(&v2);
    }
    __syncthreads();

    const uint32_t a_loff = (uint32_t)(((lane & 7) + ((lane >> 3) & 1) * 8) * SPADB
                                       + ((lane >> 4) & 1) * 16);
    const uint32_t fbase = sbase + a_loff
        + (uint32_t)((rowsel * 130 + xwbase) * SPADB);
    const uint4* wp0 = reinterpret_cast<const uint4*>(g_wpack) + lane * 2;

    float acc[4][4][4];
    #pragma unroll
    for (int mf = 0; mf < 4; mf++)
        #pragma unroll
        for (int nf = 0; nf < 4; nf++)
            #pragma unroll
            for (int r = 0; r < 4; r++) acc[mf][nf][r] = 0.f;

    uint32_t bwq[2][8];
    {
        const uint4* p = wp0 + (size_t)warpN * 64;
        uint4 q0 = p[0], q1 = p[1];
        bwq[0][0] = q0.x; bwq[0][1] = q0.y; bwq[0][2] = q0.z; bwq[0][3] = q0.w;
        bwq[0][4] = q1.x; bwq[0][5] = q1.y; bwq[0][6] = q1.z; bwq[0][7] = q1.w;
    }

    #pragma unroll
    for (int i = 0; i < 36; i++) {
        const int t  = i >> 2, kc = i & 3;
        const int ky = t / 3,  kx = t - ky * 3;
        const uint32_t frow = fbase
            + (uint32_t)((ky * 130 + kx) * SPADB + kc * 32);
        uint32_t a[4][4];
        #pragma unroll
        for (int mf = 0; mf < 4; mf++)
            ldmx4(a[mf], frow + (uint32_t)(mf * 16 * SPADB));

        if (i < 35) {
            const int u = (i + 1) * 2 + warpN;
            const uint4* p = wp0 + (size_t)u * 64;
            uint4 q0 = p[0], q1 = p[1];
            uint32_t* dst = bwq[(i + 1) & 1];
            dst[0] = q0.x; dst[1] = q0.y; dst[2] = q0.z; dst[3] = q0.w;
            dst[4] = q1.x; dst[5] = q1.y; dst[6] = q1.z; dst[7] = q1.w;
        }

        const uint32_t* bf = bwq[i & 1];
        #pragma unroll
        for (int nf = 0; nf < 4; nf++)
            #pragma unroll
            for (int mf = 0; mf < 4; mf++)
                mma_bf16(acc[mf][nf], a[mf], bf[nf * 2], bf[nf * 2 + 1]);
    }

    const int yy = y0 + rowsel;
    #pragma unroll
    for (int nf = 0; nf < 4; nf++) {
        const int co = warpN * 32 + nf * 8 + tig * 2;
        #pragma unroll
        for (int mf = 0; mf < 4; mf++) {
            const int xg = x0 + xwbase + mf * 16 + gid;
            size_t base = (((size_t)b * H_ + yy) * W_ + xg) * C_ + co;
            if (xg < W_) {
                __nv_bfloat162 v = __floats2bfloat162_rn(
                    fmaxf(acc[mf][nf][0], 0.f), fmaxf(acc[mf][nf][1], 0.f));
                *reinterpret_cast<uint32_t*>(&g_h[base]) =
                    *reinterpret_cast<uint32_t*>(&v);
            }
            if (xg + 8 < W_) {
                __nv_bfloat162 v = __floats2bfloat162_rn(
                    fmaxf(acc[mf][nf][2], 0.f), fmaxf(acc[mf][nf][3], 0.f));
                *reinterpret_cast<uint32_t*>(&g_h[base + 8 * C_]) =
                    *reinterpret_cast<uint32_t*>(&v);
            }
        }
    }
}

// ---------------------------------------------------------------------------
// Kernel B: 1x1 conv (64->144) via bf16 mma + softmax(9 taps) + depth blend
// + pixel shuffle. CTA = 64 px of one row, 256 threads (8 warps) — the R11
// configuration (measured 96.7us). Logits alias staging; 4 CTAs/SM.
// ---------------------------------------------------------------------------
#define SHB_OFF   0            // h tile  [64 px][72 bf16]  9216 B   (aliased)
#define SWB_OFF   9216         // w2      [144 co][72 bf16] 20736 B  (aliased)
#define SLOG_OFF  0            // logits  [64][146] f32     37376 B  (aliases above)
#define SDEP_OFF  37376        // depth   [3][66] f32         792 B
#define SMEM_B_BYTES 38168

__global__ __launch_bounds__(256, 4) void mask_upsample_kernel(
    const float* __restrict__ depth, const float* __restrict__ w2,
    float* __restrict__ out)
{
    extern __shared__ char smB[];
    char*  shb  = smB + SHB_OFF;
    char*  swb  = smB + SWB_OFF;
    float* slog = reinterpret_cast<float*>(smB + SLOG_OFF);
    float (*sdep)[66] = reinterpret_cast<float(*)[66]>(smB + SDEP_OFF);

    const int x0  = (blockIdx.x < 6) ? blockIdx.x * 64 : (W_ - 64);
    const int y   = blockIdx.y;
    const int b   = blockIdx.z;
    const int tid = threadIdx.x;
    const int wid = tid >> 5;
    const int lane = tid & 31;
    const int gid = lane >> 2;
    const int tig = lane & 3;
    const int warpM = wid & 3;
    const int warpN = wid >> 2;

    for (int j = tid; j < 64 * 8; j += 256) {
        int px = j >> 3, seg = j & 7;
        int gx = x0 + px;
        uint4 v = make_uint4(0u, 0u, 0u, 0u);
        if (gx < W_)
            v = *reinterpret_cast<const uint4*>(
                g_h + ((((size_t)b * H_ + y) * W_ + gx) * C_ + seg * 8));
        *reinterpret_cast<uint4*>(shb + px * SPADB + seg * 16) = v;
    }
    for (int j = tid; j < 144 * 32; j += 256) {
        int co = j >> 5, ci2 = j & 31;
        const float* wp = w2 + co * 64 + ci2 * 2;
        __nv_bfloat162 v2 = __floats2bfloat162_rn(wp[0], wp[1]);
        *reinterpret_cast<uint32_t*>(swb + co * SPADB + ci2 * 4) =
            *reinterpret_cast<uint32_t*>(&v2);
    }
    for (int i = tid; i < 3 * 66; i += 256) {
        int ry = i / 66, rx = i - ry * 66;
        int gy = y + ry - 1, gx = x0 + rx - 1;
        sdep[ry][rx] = (gy >= 0 && gy < H_ && gx >= 0 && gx < W_)
                       ? depth[((size_t)b * H_ + gy) * W_ + gx] : 0.f;
    }
    __syncthreads();

    float acc[9][4];
    #pragma unroll
    for (int nf = 0; nf < 9; nf++)
        #pragma unroll
        for (int r = 0; r < 4; r++) acc[nf][r] = 0.f;

    #pragma unroll
    for (int kc = 0; kc < 4; kc++) {
        uint32_t a[4];
        const char* ap = shb + (warpM * 16 + gid) * SPADB + kc * 32 + tig * 4;
        a[0] = *reinterpret_cast<const uint32_t*>(ap);
        a[1] = *reinterpret_cast<const uint32_t*>(ap + 8 * SPADB);
        a[2] = *reinterpret_cast<const uint32_t*>(ap + 16);
        a[3] = *reinterpret_cast<const uint32_t*>(ap + 8 * SPADB + 16);
        #pragma unroll
        for (int nf = 0; nf < 9; nf++) {
            const int co = warpN * 72 + nf * 8 + gid;
            const char* bp = swb + co * SPADB + kc * 32 + tig * 4;
            uint32_t b0 = *reinterpret_cast<const uint32_t*>(bp);
            uint32_t b1 = *reinterpret_cast<const uint32_t*>(bp + 16);
            mma_bf16(acc[nf], a, b0, b1);
        }
    }

    __syncthreads();
    {
        const int px = warpM * 16 + gid;
        #pragma unroll
        for (int nf = 0; nf < 9; nf++) {
            const int co = warpN * 72 + nf * 8 + tig * 2;
            *reinterpret_cast<float2*>(&slog[px * 146 + co]) =
                make_float2(acc[nf][0], acc[nf][1]);
            *reinterpret_cast<float2*>(&slog[(px + 8) * 146 + co]) =
                make_float2(acc[nf][2], acc[nf][3]);
        }
    }
    __syncthreads();

    const int px   = tid & 63;
    const int cgrp = tid >> 6;
    float d[9];
    #pragma unroll
    for (int t = 0; t < 9; t++) d[t] = sdep[t / 3][px + (t % 3)];

    float vals[4];
    #pragma unroll
    for (int j = 0; j < 4; j++) {
        const int cell = cgrp * 4 + j;
        float lg[9];
        #pragma unroll
        for (int t = 0; t < 9; t++) lg[t] = slog[px * 146 + t * 16 + cell];
        float mx = lg[0];
        #pragma unroll
        for (int t = 1; t < 9; t++) mx = fmaxf(mx, lg[t]);
        float s = 0.f, v = 0.f;
        #pragma unroll
        for (int t = 0; t < 9; t++) {
            float e = __expf(lg[t] - mx);
            s += e;
            v = fmaf(e, d[t], v);
        }
        vals[j] = v / s;
    }

    const int gx = x0 + px;
    if (gx < W_)
        *reinterpret_cast<float4*>(
            &out[((size_t)b * OH_ + (y * 4 + cgrp)) * OW_ + gx * 4]) =
            make_float4(vals[0], vals[1], vals[2], vals[3]);
}

extern "C" void kernel_launch(void* const* d_in, const int* in_sizes, int n_in,
                              void* d_out, int out_size)
{
    const float* depth = (const float*)d_in[0];
    const float* feat  = (const float*)d_in[1];
    const float* w1    = (const float*)d_in[2];
    const float* w2    = (const float*)d_in[3];
    float* out = (float*)d_out;

    cudaFuncSetAttribute(repack_w1_kernel,
                         cudaFuncAttributeMaxDynamicSharedMemorySize, SMEM_W_BYTES);
    cudaFuncSetAttribute(conv3x3_tc_kernel,
                         cudaFuncAttributeMaxDynamicSharedMemorySize, SMEM_A_BYTES);
    cudaFuncSetAttribute(mask_upsample_kernel,
                         cudaFuncAttributeMaxDynamicSharedMemorySize, SMEM_B_BYTES);

    repack_w1_kernel<<<9, 256, SMEM_W_BYTES>>>(w1);

    dim3 gA(4, H_ / 2, B_);                   // 4 x-tiles x 64 y-pairs x 8
    conv3x3_tc_kernel<<<gA, 256, SMEM_A_BYTES>>>(feat);

    dim3 gB(7, H_, B_);                       // 7 x-tiles of 64 px (last clamped)
    mask_upsample_kernel<<<gB, 256, SMEM_B_BYTES>>>(depth, w2, out);
}

// round 14
// speedup vs baseline: 1.5486x; 1.5486x over previous
#include <cuda_runtime.h>
#include <cuda_bf16.h>
#include <cstdint>

#define B_   8
#define C_   64
#define H_   128
#define W_   416
#define OH_  (4 * H_)
#define OW_  (4 * W_)
#define HW_  (H_ * W_)

// Scratch h: conv3x3+relu output, CHANNEL-LAST bf16: [b][y][x][ci] (~54.5 MB).
__device__ __nv_bfloat16 g_h[(size_t)B_ * H_ * W_ * C_];
// Pre-built B-fragment table: [(tap*4+kc)*2+warpN][lane][8] uint32 (72 KB).
__device__ uint32_t g_wpack[72 * 32 * 8];

// ---------------------------------------------------------------------------
// helpers (legacy mma.sync / ldmatrix — compile for plain compute_103)
// ---------------------------------------------------------------------------
__device__ __forceinline__ uint32_t smem_u32(const void* p) {
    uint32_t a;
    asm("{ .reg .u64 t; cvta.to.shared.u64 t, %1; cvt.u32.u64 %0, t; }"
        : "=r"(a) : "l"(p));
    return a;
}

__device__ __forceinline__ void mma_bf16(float* d, const uint32_t* a,
                                         uint32_t b0, uint32_t b1) {
    asm volatile(
        "mma.sync.aligned.m16n8k16.row.col.f32.bf16.bf16.f32 "
        "{%0,%1,%2,%3}, {%4,%5,%6,%7}, {%8,%9}, {%0,%1,%2,%3};"
        : "+f"(d[0]), "+f"(d[1]), "+f"(d[2]), "+f"(d[3])
        : "r"(a[0]), "r"(a[1]), "r"(a[2]), "r"(a[3]), "r"(b0), "r"(b1));
}

__device__ __forceinline__ void ldmx4(uint32_t* r, uint32_t addr) {
    asm volatile(
        "ldmatrix.sync.aligned.m8n8.x4.shared.b16 {%0,%1,%2,%3}, [%4];"
        : "=r"(r[0]), "=r"(r[1]), "=r"(r[2]), "=r"(r[3]) : "r"(addr));
}

#define SPADB  144                      // bytes per ci-row (72 bf16 slots)
#define WTAP   9216                     // per-tap weights: 64*144

// ---------------------------------------------------------------------------
// Kernel W: repack w1 into per-lane B-fragment words via real ldmatrix.
// 9 CTAs (one per tap); each stages its 9KB tap tile, 8 warps each emit one
// (kc, warpN) unit.  (R12-measured: 8.7us)
// ---------------------------------------------------------------------------
#define SMEM_W_BYTES WTAP

__global__ __launch_bounds__(256) void repack_w1_kernel(
    const float* __restrict__ w1)
{
    extern __shared__ char smw[];
    const uint32_t sbase = smem_u32(smw);
    const int tap = blockIdx.x;
    const int tid = threadIdx.x;
    const int wid = tid >> 5;
    const int lane = tid & 31;

    for (int j = tid; j < 64 * 32; j += 256) {
        int co  = j >> 5;
        int ci2 = j & 31;
        const float* wp = w1 + co * 576 + ci2 * 18 + tap;
        __nv_bfloat162 v2 = __floats2bfloat162_rn(wp[0], wp[9]);
        *reinterpret_cast<uint32_t*>(smw + co * SPADB + ci2 * 4) =
            *reinterpret_cast<uint32_t*>(&v2);
    }
    __syncthreads();

    const uint32_t b_loff = (uint32_t)((lane & 7) * SPADB + ((lane >> 3) & 1) * 16
                                       + ((lane >> 4) & 1) * (8 * SPADB));
    const int kc = wid >> 1;
    const int wn = wid & 1;
    const uint32_t wrow = sbase + (uint32_t)(wn * 32 * SPADB + kc * 32) + b_loff;
    uint32_t bf[8];
    ldmx4(bf, wrow);
    ldmx4(bf + 4, wrow + (uint32_t)(16 * SPADB));
    const int u = tap * 8 + kc * 2 + wn;     // == (tap*4+kc)*2 + wn
    uint32_t* dst = g_wpack + (size_t)u * 256 + lane * 8;
    *reinterpret_cast<uint4*>(dst)     = make_uint4(bf[0], bf[1], bf[2], bf[3]);
    *reinterpret_cast<uint4*>(dst + 4) = make_uint4(bf[4], bf[5], bf[6], bf[7]);
}

// ---------------------------------------------------------------------------
// Kernel A: conv3x3 (pad=1, no bias) + ReLU as bf16 implicit GEMM.
// EXACT R11 form (measured ~151us): CTA = 2 rows x 128 px x 64 co, 256 thr
// (8 warps: 4M x 2N), 2 CTAs/SM. Scalar staging; A-frags via ldmatrix;
// B-frags via 2 coalesced LDG.128 from g_wpack, double-buffered.
// ---------------------------------------------------------------------------
#define SMEM_A_BYTES (4 * 130 * SPADB)      // 74880

__global__ __launch_bounds__(256, 2) void conv3x3_tc_kernel(
    const float* __restrict__ feat)
{
    extern __shared__ char sm[];
    const uint32_t sbase = smem_u32(sm);

    const int x0  = (blockIdx.x < 3) ? blockIdx.x * 128 : (W_ - 128);
    const int y0  = blockIdx.y * 2;
    const int b   = blockIdx.z;
    const int tid = threadIdx.x;
    const int wid = tid >> 5;
    const int lane = tid & 31;
    const int gid = lane >> 2;
    const int tig = lane & 3;

    const int warpM  = wid & 3;
    const int warpN  = wid >> 2;
    const int rowsel = warpM >> 1;
    const int xwbase = (warpM & 1) * 64;

    for (int j = tid; j < 4 * 32 * 130; j += 256) {
        int r   = j / (32 * 130);
        int rem = j - r * (32 * 130);
        int ci2 = rem / 130;
        int xi  = rem - ci2 * 130;
        int yy  = y0 + r - 1;
        int gx  = x0 + xi - 1;
        float f0 = 0.f, f1 = 0.f;
        if ((unsigned)yy < (unsigned)H_ && (unsigned)gx < (unsigned)W_) {
            size_t o = ((size_t)(b * C_ + 2 * ci2) * H_ + yy) * W_ + gx;
            f0 = feat[o];
            f1 = feat[o + (size_t)HW_];
        }
        __nv_bfloat162 v2 = __floats2bfloat162_rn(f0, f1);
        *reinterpret_cast<uint32_t*>(sm + (r * 130 + xi) * SPADB + ci2 * 4) =
            *reinterpret_cast<uint32_t*>(&v2);
    }
    __syncthreads();

    const uint32_t a_loff = (uint32_t)(((lane & 7) + ((lane >> 3) & 1) * 8) * SPADB
                                       + ((lane >> 4) & 1) * 16);
    const uint32_t fbase = sbase + a_loff
        + (uint32_t)((rowsel * 130 + xwbase) * SPADB);
    const uint4* wp0 = reinterpret_cast<const uint4*>(g_wpack) + lane * 2;

    float acc[4][4][4];
    #pragma unroll
    for (int mf = 0; mf < 4; mf++)
        #pragma unroll
        for (int nf = 0; nf < 4; nf++)
            #pragma unroll
            for (int r = 0; r < 4; r++) acc[mf][nf][r] = 0.f;

    uint32_t bwq[2][8];
    {
        const uint4* p = wp0 + (size_t)warpN * 64;
        uint4 q0 = p[0], q1 = p[1];
        bwq[0][0] = q0.x; bwq[0][1] = q0.y; bwq[0][2] = q0.z; bwq[0][3] = q0.w;
        bwq[0][4] = q1.x; bwq[0][5] = q1.y; bwq[0][6] = q1.z; bwq[0][7] = q1.w;
    }

    #pragma unroll
    for (int i = 0; i < 36; i++) {
        const int t  = i >> 2, kc = i & 3;
        const int ky = t / 3,  kx = t - ky * 3;
        const uint32_t frow = fbase
            + (uint32_t)((ky * 130 + kx) * SPADB + kc * 32);
        uint32_t a[4][4];
        #pragma unroll
        for (int mf = 0; mf < 4; mf++)
            ldmx4(a[mf], frow + (uint32_t)(mf * 16 * SPADB));

        if (i < 35) {
            const int u = (i + 1) * 2 + warpN;
            const uint4* p = wp0 + (size_t)u * 64;
            uint4 q0 = p[0], q1 = p[1];
            uint32_t* dst = bwq[(i + 1) & 1];
            dst[0] = q0.x; dst[1] = q0.y; dst[2] = q0.z; dst[3] = q0.w;
            dst[4] = q1.x; dst[5] = q1.y; dst[6] = q1.z; dst[7] = q1.w;
        }

        const uint32_t* bf = bwq[i & 1];
        #pragma unroll
        for (int nf = 0; nf < 4; nf++)
            #pragma unroll
            for (int mf = 0; mf < 4; mf++)
                mma_bf16(acc[mf][nf], a[mf], bf[nf * 2], bf[nf * 2 + 1]);
    }

    const int yy = y0 + rowsel;
    #pragma unroll
    for (int nf = 0; nf < 4; nf++) {
        const int co = warpN * 32 + nf * 8 + tig * 2;
        #pragma unroll
        for (int mf = 0; mf < 4; mf++) {
            const int xg = x0 + xwbase + mf * 16 + gid;
            size_t base = (((size_t)b * H_ + yy) * W_ + xg) * C_ + co;
            if (xg < W_) {
                __nv_bfloat162 v = __floats2bfloat162_rn(
                    fmaxf(acc[mf][nf][0], 0.f), fmaxf(acc[mf][nf][1], 0.f));
                *reinterpret_cast<uint32_t*>(&g_h[base]) =
                    *reinterpret_cast<uint32_t*>(&v);
            }
            if (xg + 8 < W_) {
                __nv_bfloat162 v = __floats2bfloat162_rn(
                    fmaxf(acc[mf][nf][2], 0.f), fmaxf(acc[mf][nf][3], 0.f));
                *reinterpret_cast<uint32_t*>(&g_h[base + 8 * C_]) =
                    *reinterpret_cast<uint32_t*>(&v);
            }
        }
    }
}

// ---------------------------------------------------------------------------
// Kernel B: 1x1 conv (64->144) via bf16 mma + softmax(9 taps) + depth blend
// + pixel shuffle. EXACT R11 form (measured 96.7us): CTA = 64 px, 256 thr,
// logits alias staging, 4 CTAs/SM.
// ---------------------------------------------------------------------------
#define SHB_OFF   0            // h tile  [64 px][72 bf16]  9216 B   (aliased)
#define SWB_OFF   9216         // w2      [144 co][72 bf16] 20736 B  (aliased)
#define SLOG_OFF  0            // logits  [64][146] f32     37376 B  (aliases above)
#define SDEP_OFF  37376        // depth   [3][66] f32         792 B
#define SMEM_B_BYTES 38168

__global__ __launch_bounds__(256, 4) void mask_upsample_kernel(
    const float* __restrict__ depth, const float* __restrict__ w2,
    float* __restrict__ out)
{
    extern __shared__ char smB[];
    char*  shb  = smB + SHB_OFF;
    char*  swb  = smB + SWB_OFF;
    float* slog = reinterpret_cast<float*>(smB + SLOG_OFF);
    float (*sdep)[66] = reinterpret_cast<float(*)[66]>(smB + SDEP_OFF);

    const int x0  = (blockIdx.x < 6) ? blockIdx.x * 64 : (W_ - 64);
    const int y   = blockIdx.y;
    const int b   = blockIdx.z;
    const int tid = threadIdx.x;
    const int wid = tid >> 5;
    const int lane = tid & 31;
    const int gid = lane >> 2;
    const int tig = lane & 3;
    const int warpM = wid & 3;
    const int warpN = wid >> 2;

    for (int j = tid; j < 64 * 8; j += 256) {
        int px = j >> 3, seg = j & 7;
        int gx = x0 + px;
        uint4 v = make_uint4(0u, 0u, 0u, 0u);
        if (gx < W_)
            v = *reinterpret_cast<const uint4*>(
                g_h + ((((size_t)b * H_ + y) * W_ + gx) * C_ + seg * 8));
        *reinterpret_cast<uint4*>(shb + px * SPADB + seg * 16) = v;
    }
    for (int j = tid; j < 144 * 32; j += 256) {
        int co = j >> 5, ci2 = j & 31;
        const float* wp = w2 + co * 64 + ci2 * 2;
        __nv_bfloat162 v2 = __floats2bfloat162_rn(wp[0], wp[1]);
        *reinterpret_cast<uint32_t*>(swb + co * SPADB + ci2 * 4) =
            *reinterpret_cast<uint32_t*>(&v2);
    }
    for (int i = tid; i < 3 * 66; i += 256) {
        int ry = i / 66, rx = i - ry * 66;
        int gy = y + ry - 1, gx = x0 + rx - 1;
        sdep[ry][rx] = (gy >= 0 && gy < H_ && gx >= 0 && gx < W_)
                       ? depth[((size_t)b * H_ + gy) * W_ + gx] : 0.f;
    }
    __syncthreads();

    float acc[9][4];
    #pragma unroll
    for (int nf = 0; nf < 9; nf++)
        #pragma unroll
        for (int r = 0; r < 4; r++) acc[nf][r] = 0.f;

    #pragma unroll
    for (int kc = 0; kc < 4; kc++) {
        uint32_t a[4];
        const char* ap = shb + (warpM * 16 + gid) * SPADB + kc * 32 + tig * 4;
        a[0] = *reinterpret_cast<const uint32_t*>(ap);
        a[1] = *reinterpret_cast<const uint32_t*>(ap + 8 * SPADB);
        a[2] = *reinterpret_cast<const uint32_t*>(ap + 16);
        a[3] = *reinterpret_cast<const uint32_t*>(ap + 8 * SPADB + 16);
        #pragma unroll
        for (int nf = 0; nf < 9; nf++) {
            const int co = warpN * 72 + nf * 8 + gid;
            const char* bp = swb + co * SPADB + kc * 32 + tig * 4;
            uint32_t b0 = *reinterpret_cast<const uint32_t*>(bp);
            uint32_t b1 = *reinterpret_cast<const uint32_t*>(bp + 16);
            mma_bf16(acc[nf], a, b0, b1);
        }
    }

    __syncthreads();
    {
        const int px = warpM * 16 + gid;
        #pragma unroll
        for (int nf = 0; nf < 9; nf++) {
            const int co = warpN * 72 + nf * 8 + tig * 2;
            *reinterpret_cast<float2*>(&slog[px * 146 + co]) =
                make_float2(acc[nf][0], acc[nf][1]);
            *reinterpret_cast<float2*>(&slog[(px + 8) * 146 + co]) =
                make_float2(acc[nf][2], acc[nf][3]);
        }
    }
    __syncthreads();

    const int px   = tid & 63;
    const int cgrp = tid >> 6;
    float d[9];
    #pragma unroll
    for (int t = 0; t < 9; t++) d[t] = sdep[t / 3][px + (t % 3)];

    float vals[4];
    #pragma unroll
    for (int j = 0; j < 4; j++) {
        const int cell = cgrp * 4 + j;
        float lg[9];
        #pragma unroll
        for (int t = 0; t < 9; t++) lg[t] = slog[px * 146 + t * 16 + cell];
        float mx = lg[0];
        #pragma unroll
        for (int t = 1; t < 9; t++) mx = fmaxf(mx, lg[t]);
        float s = 0.f, v = 0.f;
        #pragma unroll
        for (int t = 0; t < 9; t++) {
            float e = __expf(lg[t] - mx);
            s += e;
            v = fmaf(e, d[t], v);
        }
        vals[j] = v / s;
    }

    const int gx = x0 + px;
    if (gx < W_)
        *reinterpret_cast<float4*>(
            &out[((size_t)b * OH_ + (y * 4 + cgrp)) * OW_ + gx * 4]) =
            make_float4(vals[0], vals[1], vals[2], vals[3]);
}

extern "C" void kernel_launch(void* const* d_in, const int* in_sizes, int n_in,
                              void* d_out, int out_size)
{
    const float* depth = (const float*)d_in[0];
    const float* feat  = (const float*)d_in[1];
    const float* w1    = (const float*)d_in[2];
    const float* w2    = (const float*)d_in[3];
    float* out = (float*)d_out;

    cudaFuncSetAttribute(repack_w1_kernel,
                         cudaFuncAttributeMaxDynamicSharedMemorySize, SMEM_W_BYTES);
    cudaFuncSetAttribute(conv3x3_tc_kernel,
                         cudaFuncAttributeMaxDynamicSharedMemorySize, SMEM_A_BYTES);
    cudaFuncSetAttribute(mask_upsample_kernel,
                         cudaFuncAttributeMaxDynamicSharedMemorySize, SMEM_B_BYTES);

    repack_w1_kernel<<<9, 256, SMEM_W_BYTES>>>(w1);

    dim3 gA(4, H_ / 2, B_);                   // 4 x-tiles x 64 y-pairs x 8
    conv3x3_tc_kernel<<<gA, 256, SMEM_A_BYTES>>>(feat);

    dim3 gB(7, H_, B_);                       // 7 x-tiles of 64 px (last clamped)
    mask_upsample_kernel<<<gB, 256, SMEM_B_BYTES>>>(depth, w2, out);
}

// round 15
// speedup vs baseline: 1.6149x; 1.0428x over previous
#include <cuda_runtime.h>
#include <cuda_bf16.h>
#include <cstdint>

#define B_   8
#define C_   64
#define H_   128
#define W_   416
#define OH_  (4 * H_)
#define OW_  (4 * W_)
#define HW_  (H_ * W_)

// Scratch h: conv3x3+relu output, CHANNEL-LAST bf16: [b][y][x][ci] (~54.5 MB).
__device__ __nv_bfloat16 g_h[(size_t)B_ * H_ * W_ * C_];
// Pre-built B-fragment table: [(tap*4+kc)*2+warpN][lane][8] uint32 (72 KB).
__device__ uint32_t g_wpack[72 * 32 * 8];

// ---------------------------------------------------------------------------
// helpers (legacy mma.sync / ldmatrix — compile for plain compute_103)
// ---------------------------------------------------------------------------
__device__ __forceinline__ uint32_t smem_u32(const void* p) {
    uint32_t a;
    asm("{ .reg .u64 t; cvta.to.shared.u64 t, %1; cvt.u32.u64 %0, t; }"
        : "=r"(a) : "l"(p));
    return a;
}

__device__ __forceinline__ void mma_bf16(float* d, const uint32_t* a,
                                         uint32_t b0, uint32_t b1) {
    asm volatile(
        "mma.sync.aligned.m16n8k16.row.col.f32.bf16.bf16.f32 "
        "{%0,%1,%2,%3}, {%4,%5,%6,%7}, {%8,%9}, {%0,%1,%2,%3};"
        : "+f"(d[0]), "+f"(d[1]), "+f"(d[2]), "+f"(d[3])
        : "r"(a[0]), "r"(a[1]), "r"(a[2]), "r"(a[3]), "r"(b0), "r"(b1));
}

__device__ __forceinline__ void ldmx4(uint32_t* r, uint32_t addr) {
    asm volatile(
        "ldmatrix.sync.aligned.m8n8.x4.shared.b16 {%0,%1,%2,%3}, [%4];"
        : "=r"(r[0]), "=r"(r[1]), "=r"(r[2]), "=r"(r[3]) : "r"(addr));
}

#define SPADB  144                      // bytes per ci-row (72 bf16 slots)
#define WTAP   9216                     // per-tap weights: 64*144

// ---------------------------------------------------------------------------
// Kernel W: repack w1 into per-lane B-fragment words via real ldmatrix.
// 9 CTAs (one per tap). (R12-measured: 8.7us)
// ---------------------------------------------------------------------------
#define SMEM_W_BYTES WTAP

__global__ __launch_bounds__(256) void repack_w1_kernel(
    const float* __restrict__ w1)
{
    extern __shared__ char smw[];
    const uint32_t sbase = smem_u32(smw);
    const int tap = blockIdx.x;
    const int tid = threadIdx.x;
    const int wid = tid >> 5;
    const int lane = tid & 31;

    for (int j = tid; j < 64 * 32; j += 256) {
        int co  = j >> 5;
        int ci2 = j & 31;
        const float* wp = w1 + co * 576 + ci2 * 18 + tap;
        __nv_bfloat162 v2 = __floats2bfloat162_rn(wp[0], wp[9]);
        *reinterpret_cast<uint32_t*>(smw + co * SPADB + ci2 * 4) =
            *reinterpret_cast<uint32_t*>(&v2);
    }
    __syncthreads();

    const uint32_t b_loff = (uint32_t)((lane & 7) * SPADB + ((lane >> 3) & 1) * 16
                                       + ((lane >> 4) & 1) * (8 * SPADB));
    const int kc = wid >> 1;
    const int wn = wid & 1;
    const uint32_t wrow = sbase + (uint32_t)(wn * 32 * SPADB + kc * 32) + b_loff;
    uint32_t bf[8];
    ldmx4(bf, wrow);
    ldmx4(bf + 4, wrow + (uint32_t)(16 * SPADB));
    const int u = tap * 8 + kc * 2 + wn;     // == (tap*4+kc)*2 + wn
    uint32_t* dst = g_wpack + (size_t)u * 256 + lane * 8;
    *reinterpret_cast<uint4*>(dst)     = make_uint4(bf[0], bf[1], bf[2], bf[3]);
    *reinterpret_cast<uint4*>(dst + 4) = make_uint4(bf[4], bf[5], bf[6], bf[7]);
}

// ---------------------------------------------------------------------------
// Kernel A: conv3x3 (pad=1, no bias) + ReLU as bf16 implicit GEMM.
// EXACT R11/R14 form (measured ~151us). Grid x is now 3 exact tiles (0..383);
// the strip x>=384 is handled by conv3x3_strip_kernel below.
// ---------------------------------------------------------------------------
#define SMEM_A_BYTES (4 * 130 * SPADB)      // 74880

__global__ __launch_bounds__(256, 2) void conv3x3_tc_kernel(
    const float* __restrict__ feat)
{
    extern __shared__ char sm[];
    const uint32_t sbase = smem_u32(sm);

    const int x0  = (blockIdx.x < 3) ? blockIdx.x * 128 : (W_ - 128);
    const int y0  = blockIdx.y * 2;
    const int b   = blockIdx.z;
    const int tid = threadIdx.x;
    const int wid = tid >> 5;
    const int lane = tid & 31;
    const int gid = lane >> 2;
    const int tig = lane & 3;

    const int warpM  = wid & 3;
    const int warpN  = wid >> 2;
    const int rowsel = warpM >> 1;
    const int xwbase = (warpM & 1) * 64;

    for (int j = tid; j < 4 * 32 * 130; j += 256) {
        int r   = j / (32 * 130);
        int rem = j - r * (32 * 130);
        int ci2 = rem / 130;
        int xi  = rem - ci2 * 130;
        int yy  = y0 + r - 1;
        int gx  = x0 + xi - 1;
        float f0 = 0.f, f1 = 0.f;
        if ((unsigned)yy < (unsigned)H_ && (unsigned)gx < (unsigned)W_) {
            size_t o = ((size_t)(b * C_ + 2 * ci2) * H_ + yy) * W_ + gx;
            f0 = feat[o];
            f1 = feat[o + (size_t)HW_];
        }
        __nv_bfloat162 v2 = __floats2bfloat162_rn(f0, f1);
        *reinterpret_cast<uint32_t*>(sm + (r * 130 + xi) * SPADB + ci2 * 4) =
            *reinterpret_cast<uint32_t*>(&v2);
    }
    __syncthreads();

    const uint32_t a_loff = (uint32_t)(((lane & 7) + ((lane >> 3) & 1) * 8) * SPADB
                                       + ((lane >> 4) & 1) * 16);
    const uint32_t fbase = sbase + a_loff
        + (uint32_t)((rowsel * 130 + xwbase) * SPADB);
    const uint4* wp0 = reinterpret_cast<const uint4*>(g_wpack) + lane * 2;

    float acc[4][4][4];
    #pragma unroll
    for (int mf = 0; mf < 4; mf++)
        #pragma unroll
        for (int nf = 0; nf < 4; nf++)
            #pragma unroll
            for (int r = 0; r < 4; r++) acc[mf][nf][r] = 0.f;

    uint32_t bwq[2][8];
    {
        const uint4* p = wp0 + (size_t)warpN * 64;
        uint4 q0 = p[0], q1 = p[1];
        bwq[0][0] = q0.x; bwq[0][1] = q0.y; bwq[0][2] = q0.z; bwq[0][3] = q0.w;
        bwq[0][4] = q1.x; bwq[0][5] = q1.y; bwq[0][6] = q1.z; bwq[0][7] = q1.w;
    }

    #pragma unroll
    for (int i = 0; i < 36; i++) {
        const int t  = i >> 2, kc = i & 3;
        const int ky = t / 3,  kx = t - ky * 3;
        const uint32_t frow = fbase
            + (uint32_t)((ky * 130 + kx) * SPADB + kc * 32);
        uint32_t a[4][4];
        #pragma unroll
        for (int mf = 0; mf < 4; mf++)
            ldmx4(a[mf], frow + (uint32_t)(mf * 16 * SPADB));

        if (i < 35) {
            const int u = (i + 1) * 2 + warpN;
            const uint4* p = wp0 + (size_t)u * 64;
            uint4 q0 = p[0], q1 = p[1];
            uint32_t* dst = bwq[(i + 1) & 1];
            dst[0] = q0.x; dst[1] = q0.y; dst[2] = q0.z; dst[3] = q0.w;
            dst[4] = q1.x; dst[5] = q1.y; dst[6] = q1.z; dst[7] = q1.w;
        }

        const uint32_t* bf = bwq[i & 1];
        #pragma unroll
        for (int nf = 0; nf < 4; nf++)
            #pragma unroll
            for (int mf = 0; mf < 4; mf++)
                mma_bf16(acc[mf][nf], a[mf], bf[nf * 2], bf[nf * 2 + 1]);
    }

    const int yy = y0 + rowsel;
    #pragma unroll
    for (int nf = 0; nf < 4; nf++) {
        const int co = warpN * 32 + nf * 8 + tig * 2;
        #pragma unroll
        for (int mf = 0; mf < 4; mf++) {
            const int xg = x0 + xwbase + mf * 16 + gid;
            size_t base = (((size_t)b * H_ + yy) * W_ + xg) * C_ + co;
            if (xg < W_) {
                __nv_bfloat162 v = __floats2bfloat162_rn(
                    fmaxf(acc[mf][nf][0], 0.f), fmaxf(acc[mf][nf][1], 0.f));
                *reinterpret_cast<uint32_t*>(&g_h[base]) =
                    *reinterpret_cast<uint32_t*>(&v);
            }
            if (xg + 8 < W_) {
                __nv_bfloat162 v = __floats2bfloat162_rn(
                    fmaxf(acc[mf][nf][2], 0.f), fmaxf(acc[mf][nf][3], 0.f));
                *reinterpret_cast<uint32_t*>(&g_h[base + 8 * C_]) =
                    *reinterpret_cast<uint32_t*>(&v);
            }
        }
    }
}

// ---------------------------------------------------------------------------
// Kernel A2: strip conv3x3+ReLU for x = 384..415. CTA = 8 rows x 32 px
// (M=256, same warp shape 4M x 2N). Pixel<->(row,x) mapping folds into
// loop-invariant per-lane base addrs; (ky,kx,kc) offsets stay uniform:
// row stride 34*SPADB, mf offsets {0,16,34,50}*SPADB. Same g_wpack B-path.
// ---------------------------------------------------------------------------
#define SSTRIDE 34
#define SMEM_S_BYTES (10 * 34 * SPADB)      // 48960

__global__ __launch_bounds__(256, 2) void conv3x3_strip_kernel(
    const float* __restrict__ feat)
{
    extern __shared__ char sm[];
    const uint32_t sbase = smem_u32(sm);

    const int y0  = blockIdx.x * 8;
    const int b   = blockIdx.y;
    const int tid = threadIdx.x;
    const int wid = tid >> 5;
    const int lane = tid & 31;
    const int gid = lane >> 2;
    const int tig = lane & 3;

    const int warpM = wid & 3;           // local rows 2*warpM, 2*warpM+1
    const int warpN = wid >> 2;

    // ---- Stage feat rows y0-1 .. y0+8, gx = 383 + xi (xi 0..33) ----
    for (int j = tid; j < 10 * 32 * 34; j += 256) {
        int r   = j / (32 * 34);
        int rem = j - r * (32 * 34);
        int ci2 = rem / 34;
        int xi  = rem - ci2 * 34;
        int yy  = y0 + r - 1;
        int gx  = 383 + xi;
        float f0 = 0.f, f1 = 0.f;
        if ((unsigned)yy < (unsigned)H_ && (unsigned)gx < (unsigned)W_) {
            size_t o = ((size_t)(b * C_ + 2 * ci2) * H_ + yy) * W_ + gx;
            f0 = feat[o];
            f1 = feat[o + (size_t)HW_];
        }
        __nv_bfloat162 v2 = __floats2bfloat162_rn(f0, f1);
        *reinterpret_cast<uint32_t*>(sm + (r * SSTRIDE + xi) * SPADB + ci2 * 4) =
            *reinterpret_cast<uint32_t*>(&v2);
    }
    __syncthreads();

    const int fr = (lane & 7) + ((lane >> 3) & 1) * 8;
    const uint32_t abase = sbase
        + (uint32_t)(((2 * warpM) * SSTRIDE + fr) * SPADB)
        + (uint32_t)(((lane >> 4) & 1) * 16);
    const uint4* wp0 = reinterpret_cast<const uint4*>(g_wpack) + lane * 2;

    float acc[4][4][4];
    #pragma unroll
    for (int mf = 0; mf < 4; mf++)
        #pragma unroll
        for (int nf = 0; nf < 4; nf++)
            #pragma unroll
            for (int r = 0; r < 4; r++) acc[mf][nf][r] = 0.f;

    uint32_t bwq[2][8];
    {
        const uint4* p = wp0 + (size_t)warpN * 64;
        uint4 q0 = p[0], q1 = p[1];
        bwq[0][0] = q0.x; bwq[0][1] = q0.y; bwq[0][2] = q0.z; bwq[0][3] = q0.w;
        bwq[0][4] = q1.x; bwq[0][5] = q1.y; bwq[0][6] = q1.z; bwq[0][7] = q1.w;
    }

    // mf offsets: mf0 (row+0,x+0), mf1 (row+0,x+16), mf2 (row+1,x+0), mf3 (row+1,x+16)
    const uint32_t mfoff[4] = {0u, 16u * SPADB,
                               (uint32_t)(SSTRIDE * SPADB),
                               (uint32_t)((SSTRIDE + 16) * SPADB)};

    #pragma unroll
    for (int i = 0; i < 36; i++) {
        const int t  = i >> 2, kc = i & 3;
        const int ky = t / 3,  kx = t - ky * 3;
        const uint32_t frow = abase
            + (uint32_t)((ky * SSTRIDE + kx) * SPADB + kc * 32);
        uint32_t a[4][4];
        #pragma unroll
        for (int mf = 0; mf < 4; mf++)
            ldmx4(a[mf], frow + mfoff[mf]);

        if (i < 35) {
            const int u = (i + 1) * 2 + warpN;
            const uint4* p = wp0 + (size_t)u * 64;
            uint4 q0 = p[0], q1 = p[1];
            uint32_t* dst = bwq[(i + 1) & 1];
            dst[0] = q0.x; dst[1] = q0.y; dst[2] = q0.z; dst[3] = q0.w;
            dst[4] = q1.x; dst[5] = q1.y; dst[6] = q1.z; dst[7] = q1.w;
        }

        const uint32_t* bf = bwq[i & 1];
        #pragma unroll
        for (int nf = 0; nf < 4; nf++)
            #pragma unroll
            for (int mf = 0; mf < 4; mf++)
                mma_bf16(acc[mf][nf], a[mf], bf[nf * 2], bf[nf * 2 + 1]);
    }

    // ---- Epilogue: row = y0 + 2*warpM + (mf>>1); x = (mf&1)*16 + gid ----
    #pragma unroll
    for (int nf = 0; nf < 4; nf++) {
        const int co = warpN * 32 + nf * 8 + tig * 2;
        #pragma unroll
        for (int mf = 0; mf < 4; mf++) {
            const int yy = y0 + 2 * warpM + (mf >> 1);
            const int xg = 384 + (mf & 1) * 16 + gid;
            size_t base = (((size_t)b * H_ + yy) * W_ + xg) * C_ + co;
            {
                __nv_bfloat162 v = __floats2bfloat162_rn(
                    fmaxf(acc[mf][nf][0], 0.f), fmaxf(acc[mf][nf][1], 0.f));
                *reinterpret_cast<uint32_t*>(&g_h[base]) =
                    *reinterpret_cast<uint32_t*>(&v);
            }
            {
                __nv_bfloat162 v = __floats2bfloat162_rn(
                    fmaxf(acc[mf][nf][2], 0.f), fmaxf(acc[mf][nf][3], 0.f));
                *reinterpret_cast<uint32_t*>(&g_h[base + 8 * C_]) =
                    *reinterpret_cast<uint32_t*>(&v);
            }
        }
    }
}

// ---------------------------------------------------------------------------
// Kernel B: 1x1 conv (64->144) via bf16 mma + softmax(9 taps) + depth blend
// + pixel shuffle. EXACT R11/R14 form (measured 96.7us).
// ---------------------------------------------------------------------------
#define SHB_OFF   0
#define SWB_OFF   9216
#define SLOG_OFF  0
#define SDEP_OFF  37376
#define SMEM_B_BYTES 38168

__global__ __launch_bounds__(256, 4) void mask_upsample_kernel(
    const float* __restrict__ depth, const float* __restrict__ w2,
    float* __restrict__ out)
{
    extern __shared__ char smB[];
    char*  shb  = smB + SHB_OFF;
    char*  swb  = smB + SWB_OFF;
    float* slog = reinterpret_cast<float*>(smB + SLOG_OFF);
    float (*sdep)[66] = reinterpret_cast<float(*)[66]>(smB + SDEP_OFF);

    const int x0  = (blockIdx.x < 6) ? blockIdx.x * 64 : (W_ - 64);
    const int y   = blockIdx.y;
    const int b   = blockIdx.z;
    const int tid = threadIdx.x;
    const int wid = tid >> 5;
    const int lane = tid & 31;
    const int gid = lane >> 2;
    const int tig = lane & 3;
    const int warpM = wid & 3;
    const int warpN = wid >> 2;

    for (int j = tid; j < 64 * 8; j += 256) {
        int px = j >> 3, seg = j & 7;
        int gx = x0 + px;
        uint4 v = make_uint4(0u, 0u, 0u, 0u);
        if (gx < W_)
            v = *reinterpret_cast<const uint4*>(
                g_h + ((((size_t)b * H_ + y) * W_ + gx) * C_ + seg * 8));
        *reinterpret_cast<uint4*>(shb + px * SPADB + seg * 16) = v;
    }
    for (int j = tid; j < 144 * 32; j += 256) {
        int co = j >> 5, ci2 = j & 31;
        const float* wp = w2 + co * 64 + ci2 * 2;
        __nv_bfloat162 v2 = __floats2bfloat162_rn(wp[0], wp[1]);
        *reinterpret_cast<uint32_t*>(swb + co * SPADB + ci2 * 4) =
            *reinterpret_cast<uint32_t*>(&v2);
    }
    for (int i = tid; i < 3 * 66; i += 256) {
        int ry = i / 66, rx = i - ry * 66;
        int gy = y + ry - 1, gx = x0 + rx - 1;
        sdep[ry][rx] = (gy >= 0 && gy < H_ && gx >= 0 && gx < W_)
                       ? depth[((size_t)b * H_ + gy) * W_ + gx] : 0.f;
    }
    __syncthreads();

    float acc[9][4];
    #pragma unroll
    for (int nf = 0; nf < 9; nf++)
        #pragma unroll
        for (int r = 0; r < 4; r++) acc[nf][r] = 0.f;

    #pragma unroll
    for (int kc = 0; kc < 4; kc++) {
        uint32_t a[4];
        const char* ap = shb + (warpM * 16 + gid) * SPADB + kc * 32 + tig * 4;
        a[0] = *reinterpret_cast<const uint32_t*>(ap);
        a[1] = *reinterpret_cast<const uint32_t*>(ap + 8 * SPADB);
        a[2] = *reinterpret_cast<const uint32_t*>(ap + 16);
        a[3] = *reinterpret_cast<const uint32_t*>(ap + 8 * SPADB + 16);
        #pragma unroll
        for (int nf = 0; nf < 9; nf++) {
            const int co = warpN * 72 + nf * 8 + gid;
            const char* bp = swb + co * SPADB + kc * 32 + tig * 4;
            uint32_t b0 = *reinterpret_cast<const uint32_t*>(bp);
            uint32_t b1 = *reinterpret_cast<const uint32_t*>(bp + 16);
            mma_bf16(acc[nf], a, b0, b1);
        }
    }

    __syncthreads();
    {
        const int px = warpM * 16 + gid;
        #pragma unroll
        for (int nf = 0; nf < 9; nf++) {
            const int co = warpN * 72 + nf * 8 + tig * 2;
            *reinterpret_cast<float2*>(&slog[px * 146 + co]) =
                make_float2(acc[nf][0], acc[nf][1]);
            *reinterpret_cast<float2*>(&slog[(px + 8) * 146 + co]) =
                make_float2(acc[nf][2], acc[nf][3]);
        }
    }
    __syncthreads();

    const int px   = tid & 63;
    const int cgrp = tid >> 6;
    float d[9];
    #pragma unroll
    for (int t = 0; t < 9; t++) d[t] = sdep[t / 3][px + (t % 3)];

    float vals[4];
    #pragma unroll
    for (int j = 0; j < 4; j++) {
        const int cell = cgrp * 4 + j;
        float lg[9];
        #pragma unroll
        for (int t = 0; t < 9; t++) lg[t] = slog[px * 146 + t * 16 + cell];
        float mx = lg[0];
        #pragma unroll
        for (int t = 1; t < 9; t++) mx = fmaxf(mx, lg[t]);
        float s = 0.f, v = 0.f;
        #pragma unroll
        for (int t = 0; t < 9; t++) {
            float e = __expf(lg[t] - mx);
            s += e;
            v = fmaf(e, d[t], v);
        }
        vals[j] = v / s;
    }

    const int gx = x0 + px;
    if (gx < W_)
        *reinterpret_cast<float4*>(
            &out[((size_t)b * OH_ + (y * 4 + cgrp)) * OW_ + gx * 4]) =
            make_float4(vals[0], vals[1], vals[2], vals[3]);
}

extern "C" void kernel_launch(void* const* d_in, const int* in_sizes, int n_in,
                              void* d_out, int out_size)
{
    const float* depth = (const float*)d_in[0];
    const float* feat  = (const float*)d_in[1];
    const float* w1    = (const float*)d_in[2];
    const float* w2    = (const float*)d_in[3];
    float* out = (float*)d_out;

    cudaFuncSetAttribute(repack_w1_kernel,
                         cudaFuncAttributeMaxDynamicSharedMemorySize, SMEM_W_BYTES);
    cudaFuncSetAttribute(conv3x3_tc_kernel,
                         cudaFuncAttributeMaxDynamicSharedMemorySize, SMEM_A_BYTES);
    cudaFuncSetAttribute(conv3x3_strip_kernel,
                         cudaFuncAttributeMaxDynamicSharedMemorySize, SMEM_S_BYTES);
    cudaFuncSetAttribute(mask_upsample_kernel,
                         cudaFuncAttributeMaxDynamicSharedMemorySize, SMEM_B_BYTES);

    repack_w1_kernel<<<9, 256, SMEM_W_BYTES>>>(w1);

    dim3 gS(H_ / 8, B_);                      // 16 row-tiles x 8 batches
    conv3x3_strip_kernel<<<gS, 256, SMEM_S_BYTES>>>(feat);

    dim3 gA(3, H_ / 2, B_);                   // 3 exact x-tiles x 64 y-pairs x 8
    conv3x3_tc_kernel<<<gA, 256, SMEM_A_BYTES>>>(feat);

    dim3 gB(7, H_, B_);                       // 7 x-tiles of 64 px (last clamped)
    mask_upsample_kernel<<<gB, 256, SMEM_B_BYTES>>>(depth, w2, out);
}